// round 1
// baseline (speedup 1.0000x reference)
#include <cuda_runtime.h>
#include <cstdint>

// Problem constants (fixed by the reference)
#define N_SRC   100000
#define N_DST   100000
#define N_EDGES 3200000
#define OUT_DIM 64

// Scratch: pre-scaled features feat[i][d] = weight[node_ids[i]][d] * cj[i]
// 100000 * 64 * 4B = 25.6 MB static device array (allocation-free).
__device__ float g_feat[(size_t)N_SRC * OUT_DIM];

// ---------------------------------------------------------------------------
// Kernel 1: feat = weight[node_ids] * cj   (float4 per thread, 16 chunks/row)
// ---------------------------------------------------------------------------
__global__ void prep_feat_kernel(const int* __restrict__ node_ids,
                                 const float* __restrict__ cj,
                                 const float* __restrict__ weight) {
    int t = blockIdx.x * blockDim.x + threadIdx.x;
    if (t >= N_SRC * (OUT_DIM / 4)) return;
    int i = t >> 4;          // row
    int c = t & 15;          // float4 chunk within row
    int nid = node_ids[i];
    float s = cj[i];
    float4 v = reinterpret_cast<const float4*>(weight + (size_t)nid * OUT_DIM)[c];
    v.x *= s; v.y *= s; v.z *= s; v.w *= s;
    reinterpret_cast<float4*>(g_feat + (size_t)i * OUT_DIM)[c] = v;
}

// ---------------------------------------------------------------------------
// Kernel 2: zero the output (poisoned to 0xAA by harness)
// ---------------------------------------------------------------------------
__global__ void zero_out_kernel(float4* __restrict__ out, int n4) {
    int t = blockIdx.x * blockDim.x + threadIdx.x;
    if (t < n4) out[t] = make_float4(0.f, 0.f, 0.f, 0.f);
}

// ---------------------------------------------------------------------------
// Kernel 3: per-edge scatter-add with vectorized reductions.
// One thread per (edge, float4-chunk): 3.2M * 16 = 51.2M threads.
// 16 consecutive threads share an edge -> index loads broadcast in-warp.
// red.global.add.v4.f32 (sm_90+) = no-return vector reduction: 4x fewer
// atomic ops than scalar atomicAdd and no destination register dependency.
// ---------------------------------------------------------------------------
__global__ void edge_scatter_kernel(const int* __restrict__ src_idx,
                                    const int* __restrict__ dst_idx,
                                    float* __restrict__ out) {
    long long t = (long long)blockIdx.x * blockDim.x + threadIdx.x;
    if (t >= (long long)N_EDGES * (OUT_DIM / 4)) return;
    int e = (int)(t >> 4);
    int c = (int)(t & 15);
    int s = src_idx[e];
    int d = dst_idx[e];
    float4 v = reinterpret_cast<const float4*>(g_feat + (size_t)s * OUT_DIM)[c];
    float* p = out + (size_t)d * OUT_DIM + c * 4;
    asm volatile("red.global.add.v4.f32 [%0], {%1, %2, %3, %4};"
                 :: "l"(p), "f"(v.x), "f"(v.y), "f"(v.z), "f"(v.w)
                 : "memory");
}

// ---------------------------------------------------------------------------
// Kernel 4: out *= ci (row-wise), in place
// ---------------------------------------------------------------------------
__global__ void scale_ci_kernel(float* __restrict__ out,
                                const float* __restrict__ ci) {
    int t = blockIdx.x * blockDim.x + threadIdx.x;
    if (t >= N_DST * (OUT_DIM / 4)) return;
    int i = t >> 4;
    int c = t & 15;
    float s = ci[i];
    float4* p = reinterpret_cast<float4*>(out + (size_t)i * OUT_DIM) + c;
    float4 v = *p;
    v.x *= s; v.y *= s; v.z *= s; v.w *= s;
    *p = v;
}

// ---------------------------------------------------------------------------
// Launch. Input order per metadata: node_ids, src_idx, dst_idx, cj, ci, weight
// ---------------------------------------------------------------------------
extern "C" void kernel_launch(void* const* d_in, const int* in_sizes, int n_in,
                              void* d_out, int out_size) {
    const int*   node_ids = (const int*)  d_in[0];
    const int*   src_idx  = (const int*)  d_in[1];
    const int*   dst_idx  = (const int*)  d_in[2];
    const float* cj       = (const float*)d_in[3];
    const float* ci       = (const float*)d_in[4];
    const float* weight   = (const float*)d_in[5];
    float*       out      = (float*)      d_out;

    const int THREADS = 256;

    // 1) feat = weight[node_ids] * cj
    {
        int n = N_SRC * (OUT_DIM / 4);
        prep_feat_kernel<<<(n + THREADS - 1) / THREADS, THREADS>>>(node_ids, cj, weight);
    }
    // 2) zero output
    {
        int n4 = (N_DST * OUT_DIM) / 4;
        zero_out_kernel<<<(n4 + THREADS - 1) / THREADS, THREADS>>>((float4*)out, n4);
    }
    // 3) scatter-add over edges
    {
        long long n = (long long)N_EDGES * (OUT_DIM / 4);
        int blocks = (int)((n + THREADS - 1) / THREADS);
        edge_scatter_kernel<<<blocks, THREADS>>>(src_idx, dst_idx, out);
    }
    // 4) out *= ci
    {
        int n = N_DST * (OUT_DIM / 4);
        scale_ci_kernel<<<(n + THREADS - 1) / THREADS, THREADS>>>(out, ci);
    }
}